// round 3
// baseline (speedup 1.0000x reference)
#include <cuda_runtime.h>
#include <cuda_bf16.h>
#include <cstdint>

// Problem constants (fixed shapes per reference)
#define OUTF 4096
#define INF  11008
#define NVEC (OUTF * (INF / 8))   // 5,636,096 code vectors
#define MDIM 4096                 // 2 * 2048 tokens
#define NDIM OUTF
#define KDIM INF

// 172 MB fp32 dequantized-weight scratch (device global: allocation-guard safe)
__device__ __align__(16) float g_w[(size_t)OUTF * INF];

// ---------------------------------------------------------------------------
// Kernel 1: dequantize  w[n][k] = codebook[indices[nk/8]][nk%8] * scales[n]
// ---------------------------------------------------------------------------
__global__ void dequant_kernel(const int* __restrict__ indices,
                               const float* __restrict__ codebook,
                               const float* __restrict__ scales) {
    int i = blockIdx.x * blockDim.x + threadIdx.x;
    if (i >= NVEC) return;
    int code = indices[i];
    const float4* cb = reinterpret_cast<const float4*>(codebook) + (size_t)code * 2;
    float4 v0 = cb[0];
    float4 v1 = cb[1];
    int row = i / (INF / 8);           // 1376 vectors per output row
    float s = __ldg(&scales[row]);
    v0.x *= s; v0.y *= s; v0.z *= s; v0.w *= s;
    v1.x *= s; v1.y *= s; v1.z *= s; v1.w *= s;
    float4* dst = reinterpret_cast<float4*>(g_w) + (size_t)i * 2;
    dst[0] = v0;
    dst[1] = v1;
}

// ---------------------------------------------------------------------------
// Kernel 2: SGEMM  C[m][n] = sum_k A[m][k] * W[n][k]
// 128x128 tile, BK=16, 256 threads, 8x8 per thread, FFMA2 (fma.rn.f32x2) inner
// ---------------------------------------------------------------------------
#define BM 128
#define BN 128
#define BK 16
#define PAD 4
#define LDA (BM + PAD)
#define LDB (BN + PAD)

__device__ __forceinline__ unsigned long long fma_f32x2(unsigned long long a,
                                                        unsigned long long b,
                                                        unsigned long long c) {
    unsigned long long d;
    asm("fma.rn.f32x2 %0, %1, %2, %3;" : "=l"(d) : "l"(a), "l"(b), "l"(c));
    return d;
}

__device__ __forceinline__ unsigned long long pack2(float lo, float hi) {
    unsigned long long r;
    asm("mov.b64 %0, {%1, %2};" : "=l"(r) : "f"(lo), "f"(hi));
    return r;
}

__global__ __launch_bounds__(256, 2)
void sgemm_kernel(const float* __restrict__ A, float* __restrict__ C) {
    __shared__ __align__(16) float As[BK][LDA];
    __shared__ __align__(16) float Bs[BK][LDB];

    const float* B = g_w;

    const int tid = threadIdx.x;
    const int bx = blockIdx.x;   // N tile index
    const int by = blockIdx.y;   // M tile index
    const int tx = tid & 15;     // 0..15 -> N microtile
    const int ty = tid >> 4;     // 0..15 -> M microtile

    // Global->smem staging: each thread loads 2x float4 from A and B
    const int lrow = tid >> 2;         // 0..63
    const int lcol = (tid & 3) << 2;   // 0,4,8,12

    const float* Ap = A + ((size_t)(by * BM + lrow)) * KDIM + lcol;
    const float* Bp = B + ((size_t)(bx * BN + lrow)) * KDIM + lcol;

    float4 ra0 = *(const float4*)(Ap);
    float4 ra1 = *(const float4*)(Ap + (size_t)64 * KDIM);
    float4 rb0 = *(const float4*)(Bp);
    float4 rb1 = *(const float4*)(Bp + (size_t)64 * KDIM);

    unsigned long long acc[8][4];
    #pragma unroll
    for (int i = 0; i < 8; i++)
        #pragma unroll
        for (int j = 0; j < 4; j++)
            acc[i][j] = 0ULL;   // f32x2 zero

    const int ntiles = KDIM / BK;   // 688
    for (int kt = 0; kt < ntiles; kt++) {
        // Stage prefetched registers into smem (transposed)
        As[lcol + 0][lrow]      = ra0.x; As[lcol + 1][lrow]      = ra0.y;
        As[lcol + 2][lrow]      = ra0.z; As[lcol + 3][lrow]      = ra0.w;
        As[lcol + 0][lrow + 64] = ra1.x; As[lcol + 1][lrow + 64] = ra1.y;
        As[lcol + 2][lrow + 64] = ra1.z; As[lcol + 3][lrow + 64] = ra1.w;
        Bs[lcol + 0][lrow]      = rb0.x; Bs[lcol + 1][lrow]      = rb0.y;
        Bs[lcol + 2][lrow]      = rb0.z; Bs[lcol + 3][lrow]      = rb0.w;
        Bs[lcol + 0][lrow + 64] = rb1.x; Bs[lcol + 1][lrow + 64] = rb1.y;
        Bs[lcol + 2][lrow + 64] = rb1.z; Bs[lcol + 3][lrow + 64] = rb1.w;
        __syncthreads();

        // Prefetch next tile (LDG latency overlapped with compute below)
        if (kt + 1 < ntiles) {
            const float* An = Ap + (size_t)(kt + 1) * BK;
            const float* Bn = Bp + (size_t)(kt + 1) * BK;
            ra0 = *(const float4*)(An);
            ra1 = *(const float4*)(An + (size_t)64 * KDIM);
            rb0 = *(const float4*)(Bn);
            rb1 = *(const float4*)(Bn + (size_t)64 * KDIM);
        }

        #pragma unroll
        for (int kk = 0; kk < BK; kk++) {
            float4 a0 = *(const float4*)&As[kk][ty * 8];
            float4 a1 = *(const float4*)&As[kk][ty * 8 + 4];
            const ulonglong2* bp = (const ulonglong2*)&Bs[kk][tx * 8];
            ulonglong2 bA = bp[0];
            ulonglong2 bB = bp[1];
            unsigned long long b2[4] = {bA.x, bA.y, bB.x, bB.y};
            float av[8] = {a0.x, a0.y, a0.z, a0.w, a1.x, a1.y, a1.z, a1.w};
            #pragma unroll
            for (int i = 0; i < 8; i++) {
                unsigned long long a2 = pack2(av[i], av[i]);
                #pragma unroll
                for (int j = 0; j < 4; j++)
                    acc[i][j] = fma_f32x2(a2, b2[j], acc[i][j]);
            }
        }
        __syncthreads();
    }

    // Epilogue: unpack f32x2 accumulators, vectorized stores
    const int crow0 = by * BM + ty * 8;
    const int ccol  = bx * BN + tx * 8;
    #pragma unroll
    for (int i = 0; i < 8; i++) {
        float out[8];
        #pragma unroll
        for (int j = 0; j < 4; j++) {
            float lo, hi;
            asm("mov.b64 {%0, %1}, %2;" : "=f"(lo), "=f"(hi) : "l"(acc[i][j]));
            out[2 * j]     = lo;
            out[2 * j + 1] = hi;
        }
        float4* cp = (float4*)(C + (size_t)(crow0 + i) * NDIM + ccol);
        cp[0] = make_float4(out[0], out[1], out[2], out[3]);
        cp[1] = make_float4(out[4], out[5], out[6], out[7]);
    }
}

// ---------------------------------------------------------------------------
// Launch: dequant -> sgemm (same stream, graph-capturable, no allocs/syncs)
// Inputs (metadata order): x fp32, indices int32, codebook fp32, scales fp32
// ---------------------------------------------------------------------------
extern "C" void kernel_launch(void* const* d_in, const int* in_sizes, int n_in,
                              void* d_out, int out_size) {
    const float* x        = (const float*)d_in[0];
    const int*   indices  = (const int*)d_in[1];
    const float* codebook = (const float*)d_in[2];
    const float* scales   = (const float*)d_in[3];
    float* out = (float*)d_out;

    dequant_kernel<<<(NVEC + 255) / 256, 256>>>(indices, codebook, scales);

    dim3 grid(NDIM / BN, MDIM / BM);   // (32, 32)
    sgemm_kernel<<<grid, 256>>>(x, out);
}

// round 5
// speedup vs baseline: 2.0747x; 2.0747x over previous
#include <cuda_runtime.h>
#include <cuda_bf16.h>
#include <cstdint>

// ---------------------------------------------------------------------------
// Problem constants
// ---------------------------------------------------------------------------
#define OUTF 4096
#define INF  11008
#define MDIM 4096                 // 2*2048 tokens
#define NDIM OUTF
#define KDIM INF
#define NVEC (OUTF * (INF / 8))   // 5,636,096 code vectors

// GEMM tiling
#define BM 128
#define BN 128
#define BK 32
#define KT (KDIM / BK)            // 344
#define MT (MDIM / BM)            // 32
#define NT (NDIM / BN)            // 32

#define TILE_G 8192               // packed gmem tile: 128 rows x 64B
#define SROW   80                 // padded smem row stride (conflict-free ldmatrix)
#define TILE_S (128 * SROW)       // 10240
#define NST 4
#define STAGE_BYTES (4 * TILE_S)  // 40960 (Ahi, Alo, Whi, Wlo)
#define SMEM_TOTAL (NST * STAGE_BYTES)   // 163840

// Packed bf16 operand tiles (static device arrays: alloc-guard safe)
__device__ __align__(256) uint8_t g_a_hi[(size_t)MT * KT * TILE_G];
__device__ __align__(256) uint8_t g_a_lo[(size_t)MT * KT * TILE_G];
__device__ __align__(256) uint8_t g_w_hi[(size_t)NT * KT * TILE_G];
__device__ __align__(256) uint8_t g_w_lo[(size_t)NT * KT * TILE_G];

// ---------------------------------------------------------------------------
// PTX helpers (all plain sm_80+ — compile at compute_103)
// ---------------------------------------------------------------------------
__device__ __forceinline__ uint32_t smem_u32(const void* p) {
    uint32_t a;
    asm("{ .reg .u64 t; cvta.to.shared.u64 t, %1; cvt.u32.u64 %0, t; }"
        : "=r"(a) : "l"(p));
    return a;
}

__device__ __forceinline__ void cp_async16(uint32_t sdst, const void* gsrc) {
    asm volatile("cp.async.cg.shared.global [%0], [%1], 16;"
                 :: "r"(sdst), "l"(gsrc) : "memory");
}
#define CP_COMMIT()  asm volatile("cp.async.commit_group;" ::: "memory")
#define CP_WAIT(n)   asm volatile("cp.async.wait_group %0;" :: "n"(n) : "memory")

__device__ __forceinline__ void ldsm4(uint32_t (&r)[4], uint32_t addr) {
    asm volatile("ldmatrix.sync.aligned.m8n8.x4.shared.b16 {%0,%1,%2,%3}, [%4];"
                 : "=r"(r[0]), "=r"(r[1]), "=r"(r[2]), "=r"(r[3]) : "r"(addr));
}

__device__ __forceinline__ void mma_bf16(float (&c)[4], const uint32_t (&a)[4],
                                         uint32_t b0, uint32_t b1) {
    asm volatile(
        "mma.sync.aligned.m16n8k16.row.col.f32.bf16.bf16.f32 "
        "{%0,%1,%2,%3}, {%4,%5,%6,%7}, {%8,%9}, {%0,%1,%2,%3};"
        : "+f"(c[0]), "+f"(c[1]), "+f"(c[2]), "+f"(c[3])
        : "r"(a[0]), "r"(a[1]), "r"(a[2]), "r"(a[3]), "r"(b0), "r"(b1));
}

// ---------------------------------------------------------------------------
// hi/lo bf16 split of 8 fp32 values -> two uint4 (16B) chunks
// ---------------------------------------------------------------------------
__device__ __forceinline__ void split8(const float* v, uint4& hi4, uint4& lo4) {
    uint32_t hi[4], lo[4];
    #pragma unroll
    for (int e = 0; e < 4; e++) {
        __nv_bfloat16 h0 = __float2bfloat16_rn(v[2 * e]);
        __nv_bfloat16 h1 = __float2bfloat16_rn(v[2 * e + 1]);
        __nv_bfloat16 l0 = __float2bfloat16_rn(v[2 * e] - __bfloat162float(h0));
        __nv_bfloat16 l1 = __float2bfloat16_rn(v[2 * e + 1] - __bfloat162float(h1));
        hi[e] = (uint32_t)__bfloat16_as_ushort(h0) | ((uint32_t)__bfloat16_as_ushort(h1) << 16);
        lo[e] = (uint32_t)__bfloat16_as_ushort(l0) | ((uint32_t)__bfloat16_as_ushort(l1) << 16);
    }
    hi4 = make_uint4(hi[0], hi[1], hi[2], hi[3]);
    lo4 = make_uint4(lo[0], lo[1], lo[2], lo[3]);
}

// ---------------------------------------------------------------------------
// Kernel 1: x (fp32 row-major) -> packed A_hi/A_lo tiles
// ---------------------------------------------------------------------------
__global__ void convert_x_kernel(const float* __restrict__ x) {
    int i = blockIdx.x * blockDim.x + threadIdx.x;    // one thread = 8 k-elems
    if (i >= MDIM * (KDIM / 8)) return;
    int m = i / (KDIM / 8);
    int k = (i % (KDIM / 8)) * 8;

    const float4* xp = reinterpret_cast<const float4*>(x + (size_t)m * KDIM + k);
    float4 v0 = xp[0], v1 = xp[1];
    float v[8] = {v0.x, v0.y, v0.z, v0.w, v1.x, v1.y, v1.z, v1.w};
    uint4 hi4, lo4;
    split8(v, hi4, lo4);

    int mt = m >> 7, r = m & 127, kt = k >> 5, c = (k & 31) >> 3;
    size_t off = ((size_t)mt * KT + kt) * TILE_G + r * 64 + c * 16;
    *reinterpret_cast<uint4*>(g_a_hi + off) = hi4;
    *reinterpret_cast<uint4*>(g_a_lo + off) = lo4;
}

// ---------------------------------------------------------------------------
// Kernel 2: dequant -> packed W_hi/W_lo tiles
// ---------------------------------------------------------------------------
__global__ void dequant_kernel(const int* __restrict__ indices,
                               const float* __restrict__ codebook,
                               const float* __restrict__ scales) {
    int i = blockIdx.x * blockDim.x + threadIdx.x;    // one thread = one 8-vector
    if (i >= NVEC) return;
    int n = i / (INF / 8);
    int k = (i % (INF / 8)) * 8;

    int code = indices[i];
    const float4* cb = reinterpret_cast<const float4*>(codebook) + (size_t)code * 2;
    float4 c0 = cb[0], c1 = cb[1];
    float s = __ldg(&scales[n]);
    float v[8] = {c0.x * s, c0.y * s, c0.z * s, c0.w * s,
                  c1.x * s, c1.y * s, c1.z * s, c1.w * s};
    uint4 hi4, lo4;
    split8(v, hi4, lo4);

    int nt = n >> 7, r = n & 127, kt = k >> 5, c = (k & 31) >> 3;
    size_t off = ((size_t)nt * KT + kt) * TILE_G + r * 64 + c * 16;
    *reinterpret_cast<uint4*>(g_w_hi + off) = hi4;
    *reinterpret_cast<uint4*>(g_w_lo + off) = lo4;
}

// ---------------------------------------------------------------------------
// Kernel 3: bf16 HMMA GEMM  C = A_hi·W_hiᵀ + A_hi·W_loᵀ + A_lo·W_hiᵀ
// 128x128 CTA, BK=32, 4-stage cp.async pipeline, warp tile 32x64 (m16n8k16)
// ---------------------------------------------------------------------------
__global__ void __launch_bounds__(256, 1)
gemm_kernel(float* __restrict__ C) {
    extern __shared__ __align__(1024) uint8_t smem[];
    const uint32_t sb = smem_u32(smem);
    const int tid = threadIdx.x;
    const int lane = tid & 31;
    const int wid = tid >> 5;
    const int wm = wid & 3;       // 4 m-warps  (32 rows each)
    const int wn = wid >> 2;      // 2 n-warps  (64 cols each)

    // grouped raster: 8 m-tiles per group for L2 reuse
    const int bid = blockIdx.x;
    const int mt = (bid >> 8) * 8 + (bid & 7);
    const int nt = (bid >> 3) & 31;

    const uint8_t* gbase[4] = {
        g_a_hi + (size_t)mt * KT * TILE_G,
        g_a_lo + (size_t)mt * KT * TILE_G,
        g_w_hi + (size_t)nt * KT * TILE_G,
        g_w_lo + (size_t)nt * KT * TILE_G,
    };

    // cp.async mapping: 2048 chunks/stage, 8 per thread
    // ch = tid + j*256 : tile=ch>>9, row=(ch&511)>>2, c=ch&3
    auto load_stage = [&](int s, int kt) {
        #pragma unroll
        for (int j = 0; j < 8; j++) {
            int ch = tid + j * 256;
            int tile = ch >> 9;
            int row = (ch & 511) >> 2;
            int c = ch & 3;
            const uint8_t* gsrc = gbase[tile] + (size_t)kt * TILE_G + row * 64 + c * 16;
            uint32_t sdst = sb + s * STAGE_BYTES + tile * TILE_S + row * SROW + c * 16;
            cp_async16(sdst, gsrc);
        }
    };

    // prologue: fill NST-1 stages
    #pragma unroll
    for (int s = 0; s < NST - 1; s++) {
        load_stage(s, s);
        CP_COMMIT();
    }
    CP_WAIT(NST - 2);
    __syncthreads();

    float acc[2][8][4];
    #pragma unroll
    for (int mi = 0; mi < 2; mi++)
        #pragma unroll
        for (int n8 = 0; n8 < 8; n8++)
            #pragma unroll
            for (int q = 0; q < 4; q++) acc[mi][n8][q] = 0.0f;

    // per-thread ldmatrix base offsets (mi=0/kh=0)
    const uint32_t a_off = (uint32_t)(wm * 32 + (lane & 15)) * SROW + (lane >> 4) * 16;
    const uint32_t w_off = (uint32_t)(wn * 64 + (lane & 15)) * SROW + (lane >> 4) * 16;

    for (int k = 0; k < KT; k++) {
        const int s = k & (NST - 1);
        const uint32_t sAhi = sb + s * STAGE_BYTES;
        const uint32_t sAlo = sAhi + TILE_S;
        const uint32_t sWhi = sAhi + 2 * TILE_S;
        const uint32_t sWlo = sAhi + 3 * TILE_S;

        uint32_t ah[2][2][4], al[2][2][4], wr[4][2][4];

        // A_hi + W_hi fragments
        #pragma unroll
        for (int mi = 0; mi < 2; mi++)
            #pragma unroll
            for (int kh = 0; kh < 2; kh++)
                ldsm4(ah[mi][kh], sAhi + a_off + mi * (16 * SROW) + kh * 32);
        #pragma unroll
        for (int ni = 0; ni < 4; ni++)
            #pragma unroll
            for (int kh = 0; kh < 2; kh++)
                ldsm4(wr[ni][kh], sWhi + w_off + ni * (16 * SROW) + kh * 32);

        // phase hh
        #pragma unroll
        for (int kh = 0; kh < 2; kh++)
            #pragma unroll
            for (int mi = 0; mi < 2; mi++)
                #pragma unroll
                for (int n8 = 0; n8 < 8; n8++)
                    mma_bf16(acc[mi][n8], ah[mi][kh],
                             wr[n8 >> 1][kh][n8 & 1], wr[n8 >> 1][kh][2 + (n8 & 1)]);

        // A_lo fragments, phase lh (A_lo x W_hi)
        #pragma unroll
        for (int mi = 0; mi < 2; mi++)
            #pragma unroll
            for (int kh = 0; kh < 2; kh++)
                ldsm4(al[mi][kh], sAlo + a_off + mi * (16 * SROW) + kh * 32);
        #pragma unroll
        for (int kh = 0; kh < 2; kh++)
            #pragma unroll
            for (int mi = 0; mi < 2; mi++)
                #pragma unroll
                for (int n8 = 0; n8 < 8; n8++)
                    mma_bf16(acc[mi][n8], al[mi][kh],
                             wr[n8 >> 1][kh][n8 & 1], wr[n8 >> 1][kh][2 + (n8 & 1)]);

        // W_lo fragments over W_hi regs, phase hl (A_hi x W_lo)
        #pragma unroll
        for (int ni = 0; ni < 4; ni++)
            #pragma unroll
            for (int kh = 0; kh < 2; kh++)
                ldsm4(wr[ni][kh], sWlo + w_off + ni * (16 * SROW) + kh * 32);
        #pragma unroll
        for (int kh = 0; kh < 2; kh++)
            #pragma unroll
            for (int mi = 0; mi < 2; mi++)
                #pragma unroll
                for (int n8 = 0; n8 < 8; n8++)
                    mma_bf16(acc[mi][n8], ah[mi][kh],
                             wr[n8 >> 1][kh][n8 & 1], wr[n8 >> 1][kh][2 + (n8 & 1)]);

        // issue next stage, advance pipeline
        const int kn = k + NST - 1;
        if (kn < KT) load_stage(kn & (NST - 1), kn);
        CP_COMMIT();
        CP_WAIT(NST - 2);
        __syncthreads();
    }

    // epilogue: fragment -> gmem (fp32)
    const int row0 = mt * BM + wm * 32 + (lane >> 2);
    const int col0 = nt * BN + wn * 64 + (lane & 3) * 2;
    #pragma unroll
    for (int mi = 0; mi < 2; mi++) {
        #pragma unroll
        for (int n8 = 0; n8 < 8; n8++) {
            float* p0 = C + (size_t)(row0 + mi * 16) * NDIM + col0 + n8 * 8;
            float* p1 = C + (size_t)(row0 + mi * 16 + 8) * NDIM + col0 + n8 * 8;
            p0[0] = acc[mi][n8][0];
            p0[1] = acc[mi][n8][1];
            p1[0] = acc[mi][n8][2];
            p1[1] = acc[mi][n8][3];
        }
    }
}

// ---------------------------------------------------------------------------
// Launch: convert -> dequant -> gemm  (graph-capturable, no allocs/syncs)
// Inputs (metadata order): x fp32, indices int32, codebook fp32, scales fp32
// ---------------------------------------------------------------------------
extern "C" void kernel_launch(void* const* d_in, const int* in_sizes, int n_in,
                              void* d_out, int out_size) {
    const float* x        = (const float*)d_in[0];
    const int*   indices  = (const int*)d_in[1];
    const float* codebook = (const float*)d_in[2];
    const float* scales   = (const float*)d_in[3];
    float* out = (float*)d_out;

    convert_x_kernel<<<(MDIM * (KDIM / 8) + 255) / 256, 256>>>(x);
    dequant_kernel<<<(NVEC + 255) / 256, 256>>>(indices, codebook, scales);

    cudaFuncSetAttribute(gemm_kernel, cudaFuncAttributeMaxDynamicSharedMemorySize,
                         SMEM_TOTAL);
    gemm_kernel<<<MT * NT, 256, SMEM_TOTAL>>>(out);
}